// round 5
// baseline (speedup 1.0000x reference)
#include <cuda_runtime.h>

#define HIDDEN   1024
#define SEQ      784
#define BATCH    512
#define NTHREADS 128
#define NWARPS   4
#define SPB      2                       // sequences per block (warp pair each)
#define E        16                      // hidden states per thread (32 lanes * 2 warps * 16 = 1024)
#define EH       (E / 2)

// tanh(x) = 1 - 2/(e^{2x}+1), with the 2/ln2 scale pre-folded into the xv
// constants (kernel computes xvK = (2/ln2)*xv directly). Saturates safely at
// +-inf (ex2->Inf => rcp->0 => +1 ; ex2->0 => rcp(1)=1 => -1): no clamps.
__device__ __forceinline__ float tanh_from_scaled(float xvK) {
    float e, rc;
    asm("ex2.approx.ftz.f32 %0, %1;" : "=f"(e) : "f"(xvK));
    asm("rcp.approx.ftz.f32 %0, %1;" : "=f"(rc) : "f"(e + 1.0f));
    return fmaf(-2.0f, rc, 1.0f);
}

// One block = TWO batch sequences; warps {0,1} own seq A (hidden 0-511 / 512-1023),
// warps {2,3} own seq B. The HiPPO bilinear step collapses (A diagonal + rank-1
// semiseparable) to ONE linear scan over hidden index i:
//   r_{i+1} = alf_i r_i + w_i,  w_i = gam_i h_i + dlt_i u        (r_0 = 0)
//   xv_i    = A1_i h_i + gam_i * (c*u - (c/2) r_i) ;  h_i = tanh(xv_i)
// (identities: A2 = c*gam, A3 = (c/2)*gam fold the u/r terms into one rho FMA).
// All multiplicative scan coefficients are time-invariant -> the 'a' half of
// the warp scan (saL ladder, eaC) is precomputed once; per step the scan runs
// on 'b' only. The scan is lower-triangular: odd warps read their pair-mate's
// warp total from smem; even warps read nothing.
__global__ void __launch_bounds__(NTHREADS)
ssm_scan_kernel(const float* __restrict__ x,
                const float* __restrict__ C,
                const float* __restrict__ W,
                const float* __restrict__ bias,
                float* __restrict__ out)
{
    __shared__ float xs[SPB * SEQ];
    __shared__ float wtb[2][SPB];      // per-pair warp-total 'b', double-buffered by t parity
    __shared__ float red[NWARPS];

    const int tid  = threadIdx.x;
    const int lane = tid & 31;
    const int wid  = tid >> 5;
    const int seq  = wid >> 1;         // 0 or 1 within block
    const int half = wid & 1;          // low/high 512 hidden elems
    const int bidx = blockIdx.x;

    // Stage both sequences (adjacent in memory -> coalesced).
    for (int i = tid; i < SPB * SEQ; i += NTHREADS) xs[i] = x[bidx * (SPB * SEQ) + i];

    const float KT = 2.885390081777927f;          // 2/ln(2)

    // ---- per-element constants, built in double (matches reference fp64 HiPPO) ----
    float alf[E], gam[E], dlt[E], A1K[E], KsH[E], h[E], w[E];
    float AH0, AH1;
    float c_f, mc2K;
    {
        const double step = 1.0 / (double)SEQ;
        const double c    = 0.5 * step;
        c_f  = (float)c;
        mc2K = (float)(-0.5 * c) * KT;
        #pragma unroll
        for (int e = 0; e < E; ++e) {
            const int    i = half * 512 + lane * E + e;
            const double q = (double)i;
            const double P = sqrt(1.0 + 2.0 * q);
            const double D = 1.0 + c * (1.0 + q);
            alf[e] = (float)((1.0 - c * q) / D);
            gam[e] = (float)(2.0 * P / D);
            dlt[e] = (float)(step * P * P / D);
            A1K[e] = (float)((1.0 - c * (1.0 + q)) / D) * KT;
            h[e]   = 0.f;
        }
        // KsH: suffix products of alf WITHIN each half [0,8) and [8,16)
        float p = 1.f;
        #pragma unroll
        for (int e = EH - 1; e >= 0; --e) { KsH[e] = p; p *= alf[e]; }
        AH0 = p;                                   // prod of alf[0..7]
        p = 1.f;
        #pragma unroll
        for (int e = E - 1; e >= EH; --e) { KsH[e] = p; p *= alf[e]; }
        AH1 = p;                                   // prod of alf[8..15]
    }

    // ---- one-time scan of the constant 'a' components (per warp) ----
    float saL[5];
    float sa = AH0 * AH1;                          // thread-total 'a'
    #pragma unroll
    for (int k = 0; k < 5; ++k) {
        saL[k] = sa;
        float ra = __shfl_up_sync(0xffffffffu, sa, 1 << k);
        if (lane >= (1 << k)) sa *= ra;
    }
    float eaC = __shfl_up_sync(0xffffffffu, sa, 1);
    if (lane == 0) eaC = 1.f;
    if (half) eaC = eaC;                           // odd warps: r_in = wtb[pair]

    // =========================== main time loop ===========================
    #pragma unroll 2
    for (int t = 0; t < SEQ; ++t) {
        const float u   = xs[seq * SEQ + t];
        const float cuK = (c_f * KT) * u;          // k*c*u

        // ---- thread-local: w_e and half-structured cb ----
        #pragma unroll
        for (int e = 0; e < E; ++e)
            w[e] = fmaf(gam[e], h[e], dlt[e] * u);
        float c0a = 0.f, c0b = 0.f, c1a = 0.f, c1b = 0.f;
        #pragma unroll
        for (int e = 0; e < EH; e += 2) {
            c0a = fmaf(KsH[e],        w[e],        c0a);
            c0b = fmaf(KsH[e + 1],    w[e + 1],    c0b);
            c1a = fmaf(KsH[EH + e],   w[EH + e],   c1a);
            c1b = fmaf(KsH[EH + e + 1], w[EH + e + 1], c1b);
        }
        const float cbH0 = c0a + c0b;              // b-total of lower half
        float sb = fmaf(cbH0, AH1, c1a + c1b);     // thread b-total

        // ---- warp inclusive scan on 'b' only ('a' ladder precomputed) ----
        #pragma unroll
        for (int k = 0; k < 5; ++k) {
            float rb = __shfl_up_sync(0xffffffffu, sb, 1 << k);
            if (lane >= (1 << k)) sb = fmaf(saL[k], rb, sb);
        }
        float eb = __shfl_up_sync(0xffffffffu, sb, 1);
        if (lane == 0) eb = 0.f;

        const int par = t & 1;                     // constant under unroll 2
        if (half == 0 && lane == 31) wtb[par][seq] = sb;  // even warps publish their total
        __syncthreads();                           // the ONLY block barrier per step

        // r entering this thread's first element (lower-triangular: even warps get 0 in)
        float r0 = half ? fmaf(eaC, wtb[par][seq], eb) : eb;
        // r entering the upper half of this thread (breaks the 16-chain in two)
        float r8 = fmaf(AH0, r0, cbH0);

        // ---- apply: two parallel 8-deep chains; xv/tanh hang off with ILP ----
        #pragma unroll
        for (int e = 0; e < EH; ++e) {
            float rhoK0 = fmaf(mc2K, r0, cuK);
            float rhoK1 = fmaf(mc2K, r8, cuK);
            float xv0 = fmaf(gam[e],      rhoK0, A1K[e]      * h[e]);
            float xv1 = fmaf(gam[EH + e], rhoK1, A1K[EH + e] * h[EH + e]);
            r0 = fmaf(alf[e],      r0, w[e]);
            r8 = fmaf(alf[EH + e], r8, w[EH + e]);
            h[e]      = tanh_from_scaled(xv0);
            h[EH + e] = tanh_from_scaled(xv1);
        }
    }

    // ---- epilogue: y_s = C . h (over this seq's 1024 elems) ; out = y*W + b ----
    float partial = 0.f;
    #pragma unroll
    for (int e = 0; e < E; ++e)
        partial = fmaf(__ldg(&C[half * 512 + lane * E + e]), h[e], partial);
    #pragma unroll
    for (int d = 16; d > 0; d >>= 1)
        partial += __shfl_down_sync(0xffffffffu, partial, d);
    if (lane == 0) red[wid] = partial;
    __syncthreads();
    if (tid < SPB) {
        float y = red[2 * tid] + red[2 * tid + 1];
        #pragma unroll
        for (int o = 0; o < 10; ++o)
            out[(bidx * SPB + tid) * 10 + o] = fmaf(y, W[o], bias[o]);
    }
}

extern "C" void kernel_launch(void* const* d_in, const int* in_sizes, int n_in,
                              void* d_out, int out_size) {
    const float* x    = (const float*)d_in[0];   // (512, 784, 1)
    const float* C    = (const float*)d_in[1];   // (1, 1024)
    const float* W    = (const float*)d_in[2];   // (1, 10)
    const float* bias = (const float*)d_in[3];   // (10,)
    float* out        = (float*)d_out;           // (512, 10)
    ssm_scan_kernel<<<BATCH / SPB, NTHREADS>>>(x, C, W, bias, out);
}